// round 1
// baseline (speedup 1.0000x reference)
#include <cuda_runtime.h>
#include <math.h>

// Problem constants
#define BATCH 256
#define M 128          // txt length (sigma dim)
#define NIMG 100       // img length (delta dim)
#define NP 104         // img padded to 8*13
#define D 768
#define DK 32          // GEMM d-chunk
#define ITERS 50
#define XS_STRIDE 132  // padded smem strides (bank behavior + 16B alignment)
#define YS_STRIDE 108

// Global scratch (static device arrays: allocation-free)
__device__ float g_A[BATCH * NP * M];     // A = exp(-2*C), [b][n][m], 13.6MB
__device__ float g_xmask[BATCH * M];      // 0 or 1e4
__device__ float g_ymask[BATCH * NP];     // 0 or 1e4 (n>=100 forced 1e4)
__device__ float g_xl[BATCH];
__device__ float g_yl[BATCH];
__device__ float g_ot[BATCH];
__device__ int   g_isU8;

// ---------------------------------------------------------------------------
// Detect whether pad arrays are uint8-bool or int32. int32-encoded 0/1 data has
// zero bytes at all positions p%4!=0; genuine byte-bool pad data does not.
// ---------------------------------------------------------------------------
__global__ void k_detect(const unsigned char* __restrict__ tp,
                         const unsigned char* __restrict__ ip) {
    __shared__ int flag;
    int t = threadIdx.x;
    if (t == 0) flag = 0;
    __syncthreads();
    int found = 0;
    for (int p = t; p < BATCH * M; p += blockDim.x)
        if ((p & 3) && tp[p]) { found = 1; break; }
    if (!found)
        for (int p = t; p < BATCH * NIMG; p += blockDim.x)
            if ((p & 3) && ip[p]) { found = 1; break; }
    if (found) atomicOr(&flag, 1);
    __syncthreads();
    if (t == 0) g_isU8 = flag;
}

// ---------------------------------------------------------------------------
// Build masks and lengths per batch.
// ---------------------------------------------------------------------------
__global__ void k_prep(const unsigned char* __restrict__ tp,
                       const unsigned char* __restrict__ ip) {
    int b = blockIdx.x, t = threadIdx.x;
    const int* tp32 = (const int*)tp;
    const int* ip32 = (const int*)ip;
    int u8 = g_isU8;
    __shared__ int cx, cy;
    if (t == 0) { cx = 0; cy = 0; }
    __syncthreads();
    if (t < M) {
        int pad = u8 ? (tp[b * M + t] != 0) : (tp32[b * M + t] != 0);
        g_xmask[b * M + t] = pad ? 1e4f : 0.f;
        if (pad) atomicAdd(&cx, 1);
    }
    if (t < NP) {
        int pad;
        if (t >= NIMG) pad = 1;
        else pad = u8 ? (ip[b * NIMG + t] != 0) : (ip32[b * NIMG + t] != 0);
        g_ymask[b * NP + t] = pad ? 1e4f : 0.f;
        if (pad && t < NIMG) atomicAdd(&cy, 1);
    }
    __syncthreads();
    if (t == 0) {
        g_xl[b] = (float)(M - cx);
        g_yl[b] = (float)(NIMG - cy);
    }
}

// ---------------------------------------------------------------------------
// Per-batch fp32 GEMM: S[n][m] = img_n . txt_m, fused row norms, then
// A = masked ? 0 : exp(2*(S*nxi*nyi - 1)).  One CTA per batch element.
// Thread (i=warp, j=lane) owns rows n=13i..13i+12 and cols m=4j..4j+3.
// ---------------------------------------------------------------------------
__global__ void __launch_bounds__(256) k_gemm(const float* __restrict__ seq) {
    __shared__ float Xs[DK * XS_STRIDE];
    __shared__ float Ys[DK * YS_STRIDE];
    __shared__ float snx[M], sny[NP];
    __shared__ __align__(16) float nxi[M];
    __shared__ float nyi[NP];

    int b = blockIdx.x;
    int tid = threadIdx.x;
    int i = tid >> 5, j = tid & 31;
    int ni = i * 13;

    if (tid < M)  snx[tid] = 0.f;
    if (tid < NP) sny[tid] = 0.f;

    const float* xb = seq + (size_t)b * 228 * D;        // txt rows [0,128)
    const float* yb = xb + (size_t)M * D;               // img rows [0,100)

    float4 acc[13];
#pragma unroll
    for (int r = 0; r < 13; r++) acc[r] = make_float4(0.f, 0.f, 0.f, 0.f);

    for (int d0 = 0; d0 < D; d0 += DK) {
        __syncthreads();
        // Load X tile transposed: Xs[dd][t]
#pragma unroll
        for (int q = 0; q < 4; q++) {
            int v = tid + 256 * q;
            int t = v >> 3, dq = v & 7;
            float4 val = *(const float4*)(xb + (size_t)t * D + d0 + 4 * dq);
            int base = 4 * dq;
            Xs[(base + 0) * XS_STRIDE + t] = val.x;
            Xs[(base + 1) * XS_STRIDE + t] = val.y;
            Xs[(base + 2) * XS_STRIDE + t] = val.z;
            Xs[(base + 3) * XS_STRIDE + t] = val.w;
        }
        // Load Y tile transposed: Ys[dd][n], rows >= NIMG zero-filled
#pragma unroll
        for (int q = 0; q < 4; q++) {
            int v = tid + 256 * q;
            if (v < NP * DK / 4) {
                int n = v >> 3, dq = v & 7;
                float4 val = make_float4(0.f, 0.f, 0.f, 0.f);
                if (n < NIMG)
                    val = *(const float4*)(yb + (size_t)n * D + d0 + 4 * dq);
                int base = 4 * dq;
                Ys[(base + 0) * YS_STRIDE + n] = val.x;
                Ys[(base + 1) * YS_STRIDE + n] = val.y;
                Ys[(base + 2) * YS_STRIDE + n] = val.z;
                Ys[(base + 3) * YS_STRIDE + n] = val.w;
            }
        }
        __syncthreads();
        // Fused norm accumulation
        if (tid < M) {
            float s = 0.f;
#pragma unroll
            for (int dd = 0; dd < DK; dd++) {
                float v = Xs[dd * XS_STRIDE + tid];
                s += v * v;
            }
            snx[tid] += s;
        } else if (tid < M + NP) {
            int n = tid - M;
            float s = 0.f;
#pragma unroll
            for (int dd = 0; dd < DK; dd++) {
                float v = Ys[dd * YS_STRIDE + n];
                s += v * v;
            }
            sny[n] += s;
        }
        // GEMM inner loop
#pragma unroll 4
        for (int dd = 0; dd < DK; dd++) {
            float4 xv = *(const float4*)&Xs[dd * XS_STRIDE + 4 * j];
#pragma unroll
            for (int r = 0; r < 13; r++) {
                float yv = Ys[dd * YS_STRIDE + ni + r];
                acc[r].x += yv * xv.x;
                acc[r].y += yv * xv.y;
                acc[r].z += yv * xv.z;
                acc[r].w += yv * xv.w;
            }
        }
    }
    __syncthreads();
    if (tid < M)  nxi[tid] = 1.f / fmaxf(sqrtf(snx[tid]), 1e-5f);
    if (tid < NP) nyi[tid] = 1.f / fmaxf(sqrtf(sny[tid]), 1e-5f);
    __syncthreads();

    float4 xm = *(const float4*)&g_xmask[b * M + 4 * j];
    float4 nx = *(const float4*)&nxi[4 * j];
#pragma unroll
    for (int r = 0; r < 13; r++) {
        int n = ni + r;
        float ym = g_ymask[b * NP + n];
        float ny = nyi[n];
        float4 a;
        a.x = (xm.x > 0.f || ym > 0.f) ? 0.f : __expf(2.f * (acc[r].x * nx.x * ny - 1.f));
        a.y = (xm.y > 0.f || ym > 0.f) ? 0.f : __expf(2.f * (acc[r].y * nx.y * ny - 1.f));
        a.z = (xm.z > 0.f || ym > 0.f) ? 0.f : __expf(2.f * (acc[r].z * nx.z * ny - 1.f));
        a.w = (xm.w > 0.f || ym > 0.f) ? 0.f : __expf(2.f * (acc[r].w * nx.w * ny - 1.f));
        *(float4*)&g_A[((size_t)(b * NP + n)) * M + 4 * j] = a;
    }
}

// ---------------------------------------------------------------------------
// IPOT: one CTA per batch. A,Q in dynamic smem (104KB). qs fused into the
// Q-update pass. Final iteration contracts C = -0.5*log(A) against T.
// ---------------------------------------------------------------------------
__global__ void __launch_bounds__(256, 2) k_ipot() {
    extern __shared__ __align__(16) float sm[];
    float* Aa = sm;              // NP*M
    float* Qq = sm + NP * M;     // NP*M
    __shared__ __align__(16) float sSigma[M];
    __shared__ float sDelta[NP];
    __shared__ float sQs[NP];
    __shared__ float sPart[2 * M];
    __shared__ float sXm[M];
    __shared__ float sYm[NP];
    __shared__ float sRed[8];

    int b = blockIdx.x, tid = threadIdx.x;
    int i = tid >> 5, j = tid & 31;

    const float4* gA4 = (const float4*)&g_A[(size_t)b * NP * M];
    float4* A4 = (float4*)Aa;
    float4* Q4 = (float4*)Qq;
    for (int f = tid; f < NP * M / 4; f += 256) {
        float4 a = gA4[f];
        A4[f] = a;
        Q4[f] = a;   // Q1 = A .* T0 = A (A already zero where masked)
    }
    if (tid < M)  sXm[tid] = g_xmask[b * M + tid];
    if (tid < NP) sYm[tid] = g_ymask[b * NP + tid];
    float xl = g_xl[b], yl = g_yl[b];
    __syncthreads();
    if (tid < M) sSigma[tid] = sXm[tid] > 0.f ? 0.f : 1.f / xl;  // sigma0
    __syncthreads();

    // Initial qs[n] = sum_m Q[n,m]*sigma[m]
    {
        float4 sg = *(const float4*)&sSigma[4 * j];
#pragma unroll
        for (int k = 0; k < 13; k++) {
            int n = i + 8 * k;
            float4 q = Q4[n * 32 + j];
            float s = q.x * sg.x + q.y * sg.y + q.z * sg.z + q.w * sg.w;
            s += __shfl_xor_sync(0xffffffffu, s, 16);
            s += __shfl_xor_sync(0xffffffffu, s, 8);
            s += __shfl_xor_sync(0xffffffffu, s, 4);
            s += __shfl_xor_sync(0xffffffffu, s, 2);
            s += __shfl_xor_sync(0xffffffffu, s, 1);
            if (j == 0) sQs[n] = s;
        }
    }
    __syncthreads();

    float ot = 0.f;
    for (int it = 0; it < ITERS; it++) {
        // delta from qs
        if (tid < NP)
            sDelta[tid] = __fdividef(1.f, yl * sQs[tid] + sYm[tid]);
        __syncthreads();

        // r[m] = sum_n delta[n]*Q[n,m] ; sigma[m] = 1/(xl*r + xmask)
        {
            int m = tid & 127, h = tid >> 7;
            int nb = h * 52;
            float r0 = 0.f, r1 = 0.f;
#pragma unroll
            for (int k = 0; k < 52; k += 2) {
                r0 += sDelta[nb + k]     * Qq[(nb + k) * M + m];
                r1 += sDelta[nb + k + 1] * Qq[(nb + k + 1) * M + m];
            }
            sPart[h * M + m] = r0 + r1;
        }
        __syncthreads();
        if (tid < M) {
            float r = sPart[tid] + sPart[M + tid];
            sSigma[tid] = __fdividef(1.f, xl * r + sXm[tid]);
        }
        __syncthreads();

        float4 sg2 = *(const float4*)&sSigma[4 * j];
        if (it < ITERS - 1) {
            // Q <- A .* Q .* delta[n] .* sigma[m], fused qs accumulation
#pragma unroll
            for (int k = 0; k < 13; k++) {
                int f = tid + 256 * k;
                int n = f >> 5;           // = warp + 8*k
                float4 q = Q4[f], a = A4[f];
                float dn = sDelta[n];
                q.x = a.x * q.x * dn * sg2.x;
                q.y = a.y * q.y * dn * sg2.y;
                q.z = a.z * q.z * dn * sg2.z;
                q.w = a.w * q.w * dn * sg2.w;
                Q4[f] = q;
                float s = q.x * sg2.x + q.y * sg2.y + q.z * sg2.z + q.w * sg2.w;
                s += __shfl_xor_sync(0xffffffffu, s, 16);
                s += __shfl_xor_sync(0xffffffffu, s, 8);
                s += __shfl_xor_sync(0xffffffffu, s, 4);
                s += __shfl_xor_sync(0xffffffffu, s, 2);
                s += __shfl_xor_sync(0xffffffffu, s, 1);
                if (j == 0) sQs[n] = s;
            }
        } else {
            // Final: ot += C[n,m] * T[n,m], C = -0.5*log(A), T = delta*Q*sigma
#pragma unroll
            for (int k = 0; k < 13; k++) {
                int f = tid + 256 * k;
                int n = f >> 5;
                float4 q = Q4[f], a = A4[f];
                float dn = sDelta[n];
                if (a.x > 0.f) ot += (-0.5f * __logf(a.x)) * q.x * dn * sg2.x;
                if (a.y > 0.f) ot += (-0.5f * __logf(a.y)) * q.y * dn * sg2.y;
                if (a.z > 0.f) ot += (-0.5f * __logf(a.z)) * q.z * dn * sg2.z;
                if (a.w > 0.f) ot += (-0.5f * __logf(a.w)) * q.w * dn * sg2.w;
            }
        }
        __syncthreads();
    }

    // Block reduce ot
    ot += __shfl_xor_sync(0xffffffffu, ot, 16);
    ot += __shfl_xor_sync(0xffffffffu, ot, 8);
    ot += __shfl_xor_sync(0xffffffffu, ot, 4);
    ot += __shfl_xor_sync(0xffffffffu, ot, 2);
    ot += __shfl_xor_sync(0xffffffffu, ot, 1);
    if (j == 0) sRed[i] = ot;
    __syncthreads();
    if (tid == 0) {
        float s = 0.f;
#pragma unroll
        for (int w = 0; w < 8; w++) s += sRed[w];
        g_ot[b] = s;
    }
}

// ---------------------------------------------------------------------------
// Final signed batch reduction -> scalar loss.
// ---------------------------------------------------------------------------
__global__ void k_final(const int* __restrict__ isc, float* __restrict__ out) {
    int t = threadIdx.x;
    __shared__ float sRed[8];
    float v = g_ot[t];
    float s = (isc[t] == 1) ? v : -v;
    s += __shfl_xor_sync(0xffffffffu, s, 16);
    s += __shfl_xor_sync(0xffffffffu, s, 8);
    s += __shfl_xor_sync(0xffffffffu, s, 4);
    s += __shfl_xor_sync(0xffffffffu, s, 2);
    s += __shfl_xor_sync(0xffffffffu, s, 1);
    if ((t & 31) == 0) sRed[t >> 5] = s;
    __syncthreads();
    if (t == 0) {
        float tot = 0.f;
#pragma unroll
        for (int w = 0; w < 8; w++) tot += sRed[w];
        out[0] = tot / (float)BATCH;
    }
}

// ---------------------------------------------------------------------------
extern "C" void kernel_launch(void* const* d_in, const int* in_sizes, int n_in,
                              void* d_out, int out_size) {
    const float* seq = (const float*)d_in[0];
    // d_in[1] input_ids, d_in[2] image_feat: unused (shapes are constants)
    const unsigned char* tp = (const unsigned char*)d_in[3];
    const unsigned char* ip = (const unsigned char*)d_in[4];
    const int* isc = (const int*)d_in[5];
    float* out = (float*)d_out;

    const int SMEM_IPOT = 2 * NP * M * (int)sizeof(float);  // 106496
    cudaFuncSetAttribute(k_ipot, cudaFuncAttributeMaxDynamicSharedMemorySize,
                         SMEM_IPOT);

    k_detect<<<1, 256>>>(tp, ip);
    k_prep<<<BATCH, 256>>>(tp, ip);
    k_gemm<<<BATCH, 256>>>(seq);
    k_ipot<<<BATCH, 256, SMEM_IPOT>>>();
    k_final<<<1, 256>>>(isc, out);
}

// round 3
// speedup vs baseline: 1.3526x; 1.3526x over previous
#include <cuda_runtime.h>
#include <cuda_bf16.h>
#include <math.h>
#include <stdint.h>

// Problem constants
#define BATCH 256
#define M 128          // txt length
#define NIMG 100       // img length
#define NP 104         // padded img length (13 * 8)
#define D 768
#define ITERS 50

// Fused-kernel staging layout (single buffer, swizzled bf16, 128B rows)
#define XHI_OFF 0u
#define XLO_OFF 16384u
#define YHI_OFF 32768u
#define YLO_OFF 46080u
#define BUF_BYTES 59392
#define DSM_FUSED (BUF_BYTES + 1024)
#define NUNITS 944     // 512 X units + 432 Y units (16 fp32 elems each)

#define SWZ(o) ((o) ^ (((o) >> 3) & 0x70))

// ---------------------------------------------------------------------------
// Global scratch (allocation-free static arrays)
// ---------------------------------------------------------------------------
__device__ float g_xmask[BATCH * M];      // 0 or 1e4
__device__ float g_ymask[BATCH * NP];     // 0 or 1e4 (n>=100 forced 1e4)
__device__ float g_xl[BATCH];
__device__ float g_yl[BATCH];
__device__ float g_ot[BATCH];
__device__ int   g_isU8;

// ---------------------------------------------------------------------------
// Helpers
// ---------------------------------------------------------------------------
__device__ __forceinline__ uint32_t smem_u32(const void* p) {
    uint32_t a;
    asm("{ .reg .u64 t; cvta.to.shared.u64 t, %1; cvt.u32.u64 %0, t; }"
        : "=r"(a) : "l"(p));
    return a;
}
__device__ __forceinline__ uint32_t pack_bf2(float a, float b) {
    unsigned short ua = __bfloat16_as_ushort(__float2bfloat16(a));
    unsigned short ub = __bfloat16_as_ushort(__float2bfloat16(b));
    return (uint32_t)ua | ((uint32_t)ub << 16);
}
__device__ __forceinline__ void ldsm4(uint32_t addr, uint32_t* r) {
    asm volatile("ldmatrix.sync.aligned.m8n8.x4.shared.b16 {%0,%1,%2,%3}, [%4];"
                 : "=r"(r[0]), "=r"(r[1]), "=r"(r[2]), "=r"(r[3]) : "r"(addr));
}
__device__ __forceinline__ void mma_bf16(float* d, const uint32_t* a,
                                         uint32_t b0, uint32_t b1) {
    asm volatile(
        "mma.sync.aligned.m16n8k16.row.col.f32.bf16.bf16.f32 "
        "{%0,%1,%2,%3},{%4,%5,%6,%7},{%8,%9},{%0,%1,%2,%3};"
        : "+f"(d[0]), "+f"(d[1]), "+f"(d[2]), "+f"(d[3])
        : "r"(a[0]), "r"(a[1]), "r"(a[2]), "r"(a[3]), "r"(b0), "r"(b1));
}

// ---------------------------------------------------------------------------
// Detect pad dtype (uint8-bool vs int32)
// ---------------------------------------------------------------------------
__global__ void k_detect(const unsigned char* __restrict__ tp,
                         const unsigned char* __restrict__ ip) {
    __shared__ int flag;
    int t = threadIdx.x;
    if (t == 0) flag = 0;
    __syncthreads();
    int found = 0;
    for (int p = t; p < BATCH * M; p += blockDim.x)
        if ((p & 3) && tp[p]) { found = 1; break; }
    if (!found)
        for (int p = t; p < BATCH * NIMG; p += blockDim.x)
            if ((p & 3) && ip[p]) { found = 1; break; }
    if (found) atomicOr(&flag, 1);
    __syncthreads();
    if (t == 0) g_isU8 = flag;
}

// ---------------------------------------------------------------------------
// Masks + lengths per batch.
// ---------------------------------------------------------------------------
__global__ void k_prep(const unsigned char* __restrict__ tp,
                       const unsigned char* __restrict__ ip) {
    int b = blockIdx.x, t = threadIdx.x;
    const int* tp32 = (const int*)tp;
    const int* ip32 = (const int*)ip;
    int u8 = g_isU8;
    __shared__ int cx, cy;
    if (t == 0) { cx = 0; cy = 0; }
    __syncthreads();
    if (t < M) {
        int pad = u8 ? (tp[b * M + t] != 0) : (tp32[b * M + t] != 0);
        g_xmask[b * M + t] = pad ? 1e4f : 0.f;
        if (pad) atomicAdd(&cx, 1);
    }
    if (t < NP) {
        int pad;
        if (t >= NIMG) pad = 1;
        else pad = u8 ? (ip[b * NIMG + t] != 0) : (ip32[b * NIMG + t] != 0);
        g_ymask[b * NP + t] = pad ? 1e4f : 0.f;
        if (pad && t < NIMG) atomicAdd(&cy, 1);
    }
    __syncthreads();
    if (t == 0) {
        g_xl[b] = (float)(M - cx);
        g_yl[b] = (float)(NIMG - cy);
    }
}

// ---------------------------------------------------------------------------
// Fused kernel: per-batch GEMM (split-bf16 mma.sync) + epilogue + IPOT with
// register-resident A/Q. One CTA (256 thr, 8 warps) per batch element.
//
// Warp w owns rows m = 16w..16w+15 and all 104 n-cols (13 m16n8k16 tiles).
// Fragment mapping (g = lane>>2, q2 = lane&3):
//   acc[t*4+0] = S[16w+g   ][8t+2q2  ]   acc[t*4+1] = S[16w+g   ][8t+2q2+1]
//   acc[t*4+2] = S[16w+g+8 ][8t+2q2  ]   acc[t*4+3] = S[16w+g+8 ][8t+2q2+1]
// ---------------------------------------------------------------------------
__global__ void __launch_bounds__(256) k_fused(const float* __restrict__ seq) {
    extern __shared__ __align__(16) char dsm[];
    __shared__ float pSq[NUNITS];
    __shared__ float sNxi[M];
    __shared__ float sNyi[NP];
    __shared__ float sYm[NP];
    __shared__ __align__(8) float sDelta[NP];
    __shared__ __align__(8) float sQsPart[8 * NP];
    __shared__ float sRed[8];

    const int b = blockIdx.x;
    const int tid = threadIdx.x;
    const int lane = tid & 31, w = tid >> 5;
    const int g = lane >> 2, q2 = lane & 3;

    uint32_t rawb = smem_u32(dsm);
    uint32_t sb = (rawb + 1023u) & ~1023u;
    char* sbuf = dsm + (sb - rawb);

    // ldsm address components (constant across chunks: single buffer)
    const int j8 = lane >> 3, sub = lane & 7;
    const uint32_t arow_off = (uint32_t)((16 * w + ((j8 & 1) << 3) + sub) * 128);
    const int acol = (j8 >> 1) * 8;   // elements
    const int bcol = j8 * 8;          // elements

    // ---------------- GEMM main loop ----------------
    float acc[52];
#pragma unroll
    for (int i = 0; i < 52; i++) acc[i] = 0.f;
    float nacc[4] = {0.f, 0.f, 0.f, 0.f};

    const float* seqb = seq + (size_t)b * 228 * D;

    for (int c = 0; c < 12; c++) {
        __syncthreads();   // previous chunk's mma finished reading buffer
        // ---- stage + convert + sumsq ----
#pragma unroll
        for (int k = 0; k < 4; k++) {
            int uu = tid + (k << 8);
            if (uu >= NUNITS) break;
            int isX = uu < 512;
            int row, seg;
            uint32_t hiBase, loBase;
            const float4* src = nullptr;
            if (isX) {
                row = uu >> 2; seg = uu & 3;
                src = (const float4*)(seqb + (size_t)row * D + c * 64 + seg * 16);
                hiBase = XHI_OFF; loBase = XLO_OFF;
            } else {
                int v = uu - 512;
                row = v >> 2; seg = v & 3;
                if (row < NIMG)
                    src = (const float4*)(seqb + (size_t)(128 + row) * D + c * 64 + seg * 16);
                hiBase = YHI_OFF; loBase = YLO_OFF;
            }
            float4 f0, f1, f2, f3;
            if (src) {
                f0 = src[0]; f1 = src[1]; f2 = src[2]; f3 = src[3];
            } else {
                f0 = f1 = f2 = f3 = make_float4(0.f, 0.f, 0.f, 0.f);
            }
            float ss = f0.x*f0.x + f0.y*f0.y + f0.z*f0.z + f0.w*f0.w
                     + f1.x*f1.x + f1.y*f1.y + f1.z*f1.z + f1.w*f1.w
                     + f2.x*f2.x + f2.y*f2.y + f2.z*f2.z + f2.w*f2.w
                     + f3.x*f3.x + f3.y*f3.y + f3.z*f3.z + f3.w*f3.w;
            nacc[k] += ss;

            uint4 hi0, hi1, lo0, lo1;
            hi0.x = pack_bf2(f0.x, f0.y); hi0.y = pack_bf2(f0.z, f0.w);
            hi0.z = pack_bf2(f1.x, f1.y); hi0.w = pack_bf2(f1.z, f1.w);
            hi1.x = pack_bf2(f2.x, f2.y); hi1.y = pack_bf2(f2.z, f2.w);
            hi1.z = pack_bf2(f3.x, f3.y); hi1.w = pack_bf2(f3.z, f3.w);
            lo0.x = pack_bf2(f0.x - __bfloat162float(__float2bfloat16(f0.x)),
                             f0.y - __bfloat162float(__float2bfloat16(f0.y)));
            lo0.y = pack_bf2(f0.z - __bfloat162float(__float2bfloat16(f0.z)),
                             f0.w - __bfloat162float(__float2bfloat16(f0.w)));
            lo0.z = pack_bf2(f1.x - __bfloat162float(__float2bfloat16(f1.x)),
                             f1.y - __bfloat162float(__float2bfloat16(f1.y)));
            lo0.w = pack_bf2(f1.z - __bfloat162float(__float2bfloat16(f1.z)),
                             f1.w - __bfloat162float(__float2bfloat16(f1.w)));
            lo1.x = pack_bf2(f2.x - __bfloat162float(__float2bfloat16(f2.x)),
                             f2.y - __bfloat162float(__float2bfloat16(f2.y)));
            lo1.y = pack_bf2(f2.z - __bfloat162float(__float2bfloat16(f2.z)),
                             f2.w - __bfloat162float(__float2bfloat16(f2.w)));
            lo1.z = pack_bf2(f3.x - __bfloat162float(__float2bfloat16(f3.x)),
                             f3.y - __bfloat162float(__float2bfloat16(f3.y)));
            lo1.w = pack_bf2(f3.z - __bfloat162float(__float2bfloat16(f3.z)),
                             f3.w - __bfloat162float(__float2bfloat16(f3.w)));

            uint32_t off0 = (uint32_t)(row * 128 + seg * 32);
            *(uint4*)(sbuf + hiBase + SWZ(off0))      = hi0;
            *(uint4*)(sbuf + hiBase + SWZ(off0 + 16)) = hi1;
            *(uint4*)(sbuf + loBase + SWZ(off0))      = lo0;
            *(uint4*)(sbuf + loBase + SWZ(off0 + 16)) = lo1;
        }
        __syncthreads();

        // ---- tensor-core compute for this chunk ----
#pragma unroll
        for (int k0 = 0; k0 < 64; k0 += 32) {
            uint32_t ah0[4], ah1[4], al0[4], al1[4];
            uint32_t offA0 = SWZ(arow_off + (uint32_t)((k0 + acol) * 2));
            uint32_t offA1 = SWZ(arow_off + (uint32_t)((k0 + 16 + acol) * 2));
            ldsm4(sb + XHI_OFF + offA0, ah0);
            ldsm4(sb + XHI_OFF + offA1, ah1);
            ldsm4(sb + XLO_OFF + offA0, al0);
            ldsm4(sb + XLO_OFF + offA1, al1);
#pragma unroll
            for (int t = 0; t < 13; t++) {
                uint32_t offB = SWZ((uint32_t)((8 * t + sub) * 128 + (k0 + bcol) * 2));
                uint32_t bh[4], bl[4];
                ldsm4(sb + YHI_OFF + offB, bh);
                ldsm4(sb + YLO_OFF + offB, bl);
                float* d = &acc[t * 4];
                mma_bf16(d, ah0, bh[0], bh[1]);
                mma_bf16(d, al0, bh[0], bh[1]);
                mma_bf16(d, ah0, bl[0], bl[1]);
                mma_bf16(d, ah1, bh[2], bh[3]);
                mma_bf16(d, al1, bh[2], bh[3]);
                mma_bf16(d, ah1, bl[2], bl[3]);
            }
        }
    }

    // ---------------- norms ----------------
    __syncthreads();
#pragma unroll
    for (int k = 0; k < 4; k++) {
        int uu = tid + (k << 8);
        if (uu < NUNITS) pSq[uu] = nacc[k];
    }
    if (tid < NP) sYm[tid] = g_ymask[b * NP + tid];
    __syncthreads();
    if (tid < M) {
        float ss = pSq[4 * tid] + pSq[4 * tid + 1] + pSq[4 * tid + 2] + pSq[4 * tid + 3];
        sNxi[tid] = 1.f / fmaxf(sqrtf(ss), 1e-5f);
    } else if (tid < M + NP) {
        int n = tid - M;
        float ss = pSq[512 + 4 * n] + pSq[512 + 4 * n + 1]
                 + pSq[512 + 4 * n + 2] + pSq[512 + 4 * n + 3];
        sNyi[n] = 1.f / fmaxf(sqrtf(ss), 1e-5f);
    }
    __syncthreads();

    // ---------------- epilogue: acc -> A (regs), Q = A ----------------
    const int m0 = 16 * w + g, m1 = m0 + 8;
    const float xm0 = g_xmask[b * M + m0];
    const float xm1 = g_xmask[b * M + m1];
    const float xl = g_xl[b], yl = g_yl[b];
    const float nx0 = sNxi[m0], nx1 = sNxi[m1];

    float Ar[52], Qr[52];
#pragma unroll
    for (int t = 0; t < 13; t++) {
        int n0 = 8 * t + 2 * q2, n1 = n0 + 1;
        float ny0 = sNyi[n0], ny1 = sNyi[n1];
        float ym0 = sYm[n0],  ym1 = sYm[n1];
        float a0 = (xm0 > 0.f || ym0 > 0.f) ? 0.f
                 : __expf(2.f * (acc[t * 4 + 0] * nx0 * ny0 - 1.f));
        float a1 = (xm0 > 0.f || ym1 > 0.f) ? 0.f
                 : __expf(2.f * (acc[t * 4 + 1] * nx0 * ny1 - 1.f));
        float a2 = (xm1 > 0.f || ym0 > 0.f) ? 0.f
                 : __expf(2.f * (acc[t * 4 + 2] * nx1 * ny0 - 1.f));
        float a3 = (xm1 > 0.f || ym1 > 0.f) ? 0.f
                 : __expf(2.f * (acc[t * 4 + 3] * nx1 * ny1 - 1.f));
        Ar[t * 4 + 0] = a0; Qr[t * 4 + 0] = a0;
        Ar[t * 4 + 1] = a1; Qr[t * 4 + 1] = a1;
        Ar[t * 4 + 2] = a2; Qr[t * 4 + 2] = a2;
        Ar[t * 4 + 3] = a3; Qr[t * 4 + 3] = a3;
    }

    // ---------------- IPOT (register-resident A/Q) ----------------
    float sig0 = xm0 > 0.f ? 0.f : 1.f / xl;
    float sig1 = xm1 > 0.f ? 0.f : 1.f / xl;

    // initial qs partials: qs[n] = sum_m Q[n][m]*sigma[m]
#pragma unroll
    for (int t = 0; t < 13; t++) {
        float qp0 = Qr[t * 4 + 0] * sig0 + Qr[t * 4 + 2] * sig1;
        float qp1 = Qr[t * 4 + 1] * sig0 + Qr[t * 4 + 3] * sig1;
        qp0 += __shfl_xor_sync(0xffffffffu, qp0, 4);
        qp0 += __shfl_xor_sync(0xffffffffu, qp0, 8);
        qp0 += __shfl_xor_sync(0xffffffffu, qp0, 16);
        qp1 += __shfl_xor_sync(0xffffffffu, qp1, 4);
        qp1 += __shfl_xor_sync(0xffffffffu, qp1, 8);
        qp1 += __shfl_xor_sync(0xffffffffu, qp1, 16);
        if (g == (t & 7)) {
            float2 v = make_float2(qp0, qp1);
            *(float2*)&sQsPart[w * NP + 8 * t + 2 * q2] = v;
        }
    }
    __syncthreads();

    float ot = 0.f;
#pragma unroll 1
    for (int it = 0; it < ITERS; it++) {
        // delta[n] from qs partials
        if (tid < NP) {
            float qs = 0.f;
#pragma unroll
            for (int ww = 0; ww < 8; ww++) qs += sQsPart[ww * NP + tid];
            sDelta[tid] = __fdividef(1.f, yl * qs + sYm[tid]);
        }
        __syncthreads();

        // r[m] = sum_n delta[n]*Q[n][m]; sigma = 1/(xl*r + xmask)
        float2 dl[13];
        float p0 = 0.f, p1 = 0.f;
#pragma unroll
        for (int t = 0; t < 13; t++) {
            dl[t] = *(const float2*)&sDelta[8 * t + 2 * q2];
            p0 += dl[t].x * Qr[t * 4 + 0] + dl[t].y * Qr[t * 4 + 1];
            p1 += dl[t].x * Qr[t * 4 + 2] + dl[t].y * Qr[t * 4 + 3];
        }
        p0 += __shfl_xor_sync(0xffffffffu, p0, 1);
        p0 += __shfl_xor_sync(0xffffffffu, p0, 2);
        p1 += __shfl_xor_sync(0xffffffffu, p1, 1);
        p1 += __shfl_xor_sync(0xffffffffu, p1, 2);
        sig0 = __fdividef(1.f, xl * p0 + xm0);
        sig1 = __fdividef(1.f, xl * p1 + xm1);

        if (it < ITERS - 1) {
            // Q <- A .* Q .* delta[n] .* sigma[m]; fused qs partials
#pragma unroll
            for (int t = 0; t < 13; t++) {
                float ds00 = dl[t].x * sig0, ds01 = dl[t].y * sig0;
                float ds10 = dl[t].x * sig1, ds11 = dl[t].y * sig1;
                float q0 = Ar[t * 4 + 0] * Qr[t * 4 + 0] * ds00;
                float q1 = Ar[t * 4 + 1] * Qr[t * 4 + 1] * ds01;
                float q2v = Ar[t * 4 + 2] * Qr[t * 4 + 2] * ds10;
                float q3 = Ar[t * 4 + 3] * Qr[t * 4 + 3] * ds11;
                Qr[t * 4 + 0] = q0; Qr[t * 4 + 1] = q1;
                Qr[t * 4 + 2] = q2v; Qr[t * 4 + 3] = q3;
                float qp0 = q0 * sig0 + q2v * sig1;
                float qp1 = q1 * sig0 + q3 * sig1;
                qp0 += __shfl_xor_sync(0xffffffffu, qp0, 4);
                qp0 += __shfl_xor_sync(0xffffffffu, qp0, 8);
                qp0 += __shfl_xor_sync(0xffffffffu, qp0, 16);
                qp1 += __shfl_xor_sync(0xffffffffu, qp1, 4);
                qp1 += __shfl_xor_sync(0xffffffffu, qp1, 8);
                qp1 += __shfl_xor_sync(0xffffffffu, qp1, 16);
                if (g == (t & 7)) {
                    float2 v = make_float2(qp0, qp1);
                    *(float2*)&sQsPart[w * NP + 8 * t + 2 * q2] = v;
                }
            }
        } else {
            // ot = sum C.*T, C = -0.5*ln(A), T = delta*Q*sigma
#pragma unroll
            for (int t = 0; t < 13; t++) {
                float a0 = Ar[t * 4 + 0], a1 = Ar[t * 4 + 1];
                float a2 = Ar[t * 4 + 2], a3 = Ar[t * 4 + 3];
                if (a0 > 0.f) ot += (-0.5f * __logf(a0)) * Qr[t * 4 + 0] * dl[t].x * sig0;
                if (a1 > 0.f) ot += (-0.5f * __logf(a1)) * Qr[t * 4 + 1] * dl[t].y * sig0;
                if (a2 > 0.f) ot += (-0.5f * __logf(a2)) * Qr[t * 4 + 2] * dl[t].x * sig1;
                if (a3 > 0.f) ot += (-0.5f * __logf(a3)) * Qr[t * 4 + 3] * dl[t].y * sig1;
            }
        }
        __syncthreads();
    }

    // block reduce ot
    ot += __shfl_xor_sync(0xffffffffu, ot, 16);
    ot += __shfl_xor_sync(0xffffffffu, ot, 8);
    ot += __shfl_xor_sync(0xffffffffu, ot, 4);
    ot += __shfl_xor_sync(0xffffffffu, ot, 2);
    ot += __shfl_xor_sync(0xffffffffu, ot, 1);
    if (lane == 0) sRed[w] = ot;
    __syncthreads();
    if (tid == 0) {
        float s = 0.f;
#pragma unroll
        for (int ww = 0; ww < 8; ww++) s += sRed[ww];
        g_ot[b] = s;
    }
}

// ---------------------------------------------------------------------------
// Final signed batch reduction -> scalar loss.
// ---------------------------------------------------------------------------
__global__ void k_final(const int* __restrict__ isc, float* __restrict__ out) {
    int t = threadIdx.x;
    __shared__ float sRed[8];
    float v = g_ot[t];
    float s = (isc[t] == 1) ? v : -v;
    s += __shfl_xor_sync(0xffffffffu, s, 16);
    s += __shfl_xor_sync(0xffffffffu, s, 8);
    s += __shfl_xor_sync(0xffffffffu, s, 4);
    s += __shfl_xor_sync(0xffffffffu, s, 2);
    s += __shfl_xor_sync(0xffffffffu, s, 1);
    if ((t & 31) == 0) sRed[t >> 5] = s;
    __syncthreads();
    if (t == 0) {
        float tot = 0.f;
#pragma unroll
        for (int w = 0; w < 8; w++) tot += sRed[w];
        out[0] = tot / (float)BATCH;
    }
}

// ---------------------------------------------------------------------------
extern "C" void kernel_launch(void* const* d_in, const int* in_sizes, int n_in,
                              void* d_out, int out_size) {
    const float* seq = (const float*)d_in[0];
    const unsigned char* tp = (const unsigned char*)d_in[3];
    const unsigned char* ip = (const unsigned char*)d_in[4];
    const int* isc = (const int*)d_in[5];
    float* out = (float*)d_out;

    cudaFuncSetAttribute(k_fused, cudaFuncAttributeMaxDynamicSharedMemorySize,
                         DSM_FUSED);

    k_detect<<<1, 256>>>(tp, ip);
    k_prep<<<BATCH, 256>>>(tp, ip);
    k_fused<<<BATCH, 256, DSM_FUSED>>>(seq);
    k_final<<<1, 256>>>(isc, out);
}